// round 6
// baseline (speedup 1.0000x reference)
#include <cuda_runtime.h>

#define DIM 2048
#define THETA 1e-18
#define REGEPS 1e-15

// first 50 primes (max 229 < DIM-1)
__constant__ int c_primes[50] = {
    2,3,5,7,11,13,17,19,23,29,31,37,41,43,47,53,59,61,67,71,
    73,79,83,89,97,101,103,107,109,113,127,131,137,139,149,151,157,163,167,173,
    179,181,191,193,197,199,211,223,227,229};

// Precomputed tables (device globals: no allocation allowed)
__device__ double g_aDiag[DIM];   // Arnold diagonal: 1 + theta*cos(2*pi*i/DIM)
__device__ double g_aOff1[DIM];   // Arnold off-1 at (k,k+1)
__device__ double g_dDiag[DIM];   // Re(n^{-s}) + prime diag correction
__device__ double g_abs_s;        // |s|

__global__ void precompute_kernel(const float* __restrict__ s_real,
                                  const float* __restrict__ s_imag) {
    int m = blockIdx.x * blockDim.x + threadIdx.x;
    if (m >= DIM) return;
    const double PI = 3.141592653589793238462643383279502884;
    double sr = (double)s_real[0];
    double si = (double)s_imag[0];

    g_aDiag[m] = 1.0 + THETA * cos(2.0 * PI * (double)m / (double)DIM);
    g_aOff1[m] = (m < DIM - 1) ? THETA * sin(PI * (2.0 * (double)m + 1.0) / (double)DIM)
                               : 0.0;

    int n = m + 1;
    double ln_n = log((double)n);
    bool isp = false;
    #pragma unroll
    for (int t = 0; t < 50; t++) isp |= (c_primes[t] == n);

    double dv = exp(-sr * ln_n) * cos(si * ln_n);   // Re(n^{-s})
    if (isp) dv += THETA * ln_n * (PI * PI / 6.0);  // * zeta(2)
    g_dDiag[m] = dv;

    if (m == 0) g_abs_s = sqrt(sr * sr + si * si);
}

// Arnold matrix element A(x,y): real symmetric, bandwidth 2
__device__ __forceinline__ double Aval(int x, int y) {
    if (y < 0 || y >= DIM) return 0.0;
    int d = x - y;
    if (d < 0) d = -d;
    if (d > 2) return 0.0;
    if (d == 0) return g_aDiag[x];
    if (d == 1) return g_aOff1[x < y ? x : y];
    return THETA * THETA * 0.8187307530779818586699355086383; // theta^2*exp(-0.2)
}

// Real part of S(i,j). Imag-only terms (prime off-diag, +-1 algebra) dropped:
// A real => A*(iX)*A purely imaginary. Nonzero only for |i-j| <= 4.
__device__ __forceinline__ double elem_re(int i, int j) {
    double sre = 0.0;
    #pragma unroll
    for (int kk = -2; kk <= 2; kk++) {
        int k = i + kk;
        if (k < 0 || k >= DIM) continue;
        double aik = Aval(i, k);
        sre += aik * g_dDiag[k] * Aval(j, k);
    }
    int d = i - j;
    if (d == 0) {
        sre += REGEPS;
    } else if (d == 2 || d == -2) {
        int mn = (i < j) ? i : j;
        sre += g_abs_s * THETA * THETA * exp(-(double)mn * 0.01);
    }
    return sre;
}

// One float4 (4 complex-real outputs) per thread: DIM*DIM/4 = 1M threads.
__global__ void fill_real_f32_vec4(float4* __restrict__ out) {
    int idx = blockIdx.x * blockDim.x + threadIdx.x;   // exact DIM*DIM/4
    int i  = idx >> 9;               // row (512 float4 per row)
    int c4 = (idx & 511) << 2;       // first column of this float4
    int e  = i - c4;

    float4 v = make_float4(0.f, 0.f, 0.f, 0.f);
    // vector [c4, c4+3] intersects band [i-5, i+5]  <=>  -5 <= e <= 8
    if (e >= -5 && e <= 8) {
        v.x = (float)elem_re(i, c4);
        v.y = (float)elem_re(i, c4 + 1);
        v.z = (float)elem_re(i, c4 + 2);
        v.w = (float)elem_re(i, c4 + 3);
    }
    out[idx] = v;
}

// Fallback (unused now that out_size == DIM*DIM is confirmed, kept for safety)
__global__ void fill_generic_f32(float* __restrict__ out, int n) {
    int idx = blockIdx.x * blockDim.x + threadIdx.x;
    if (idx >= n) return;
    int m = idx & (DIM * DIM - 1);
    out[idx] = (float)elem_re(m >> 11, m & (DIM - 1));
}

extern "C" void kernel_launch(void* const* d_in, const int* in_sizes, int n_in,
                              void* d_out, int out_size) {
    const float* s_real = (const float*)d_in[0];
    const float* s_imag = (const float*)((n_in >= 2) ? d_in[1] : d_in[0]);

    precompute_kernel<<<(DIM + 255) / 256, 256>>>(s_real, s_imag);

    const int NTOT = DIM * DIM;
    if (out_size == NTOT) {
        fill_real_f32_vec4<<<(NTOT / 4) / 256, 256>>>((float4*)d_out);
    } else {
        fill_generic_f32<<<(out_size + 255) / 256, 256>>>((float*)d_out, out_size);
    }
}

// round 8
// speedup vs baseline: 1.2939x; 1.2939x over previous
#include <cuda_runtime.h>

#define DIM 2048
#define THETA 1e-18
#define REGEPS 1e-15

// first 50 primes (max 229 < DIM-1)
__constant__ int c_primes[50] = {
    2,3,5,7,11,13,17,19,23,29,31,37,41,43,47,53,59,61,67,71,
    73,79,83,89,97,101,103,107,109,113,127,131,137,139,149,151,157,163,167,173,
    179,181,191,193,197,199,211,223,227,229};

// Precomputed tables (device globals: no allocation allowed)
__device__ double g_aDiag[DIM];   // Arnold diagonal: 1 + theta*cos(2*pi*i/DIM)
__device__ double g_aOff1[DIM];   // Arnold off-1 at (k,k+1)
__device__ double g_dDiag[DIM];   // Re(n^{-s}) + prime diag correction
__device__ double g_exp2[DIM];    // |s| * theta^2 * exp(-0.01*m)  (algebra |d|=2 term)

__global__ void precompute_kernel(const float* __restrict__ s_real,
                                  const float* __restrict__ s_imag) {
    int m = blockIdx.x * blockDim.x + threadIdx.x;
    if (m >= DIM) return;
    const double PI = 3.141592653589793238462643383279502884;
    double sr = (double)s_real[0];
    double si = (double)s_imag[0];

    g_aDiag[m] = 1.0 + THETA * cos(2.0 * PI * (double)m / (double)DIM);
    g_aOff1[m] = (m < DIM - 1) ? THETA * sin(PI * (2.0 * (double)m + 1.0) / (double)DIM)
                               : 0.0;

    int n = m + 1;
    double ln_n = log((double)n);
    bool isp = false;
    #pragma unroll
    for (int t = 0; t < 50; t++) isp |= (c_primes[t] == n);

    double dv = exp(-sr * ln_n) * cos(si * ln_n);   // Re(n^{-s})
    if (isp) dv += THETA * ln_n * (PI * PI / 6.0);  // * zeta(2)
    g_dDiag[m] = dv;

    double abss = sqrt(sr * sr + si * si);
    g_exp2[m] = abss * THETA * THETA * exp(-0.01 * (double)m);
}

// Arnold matrix element A(x,y): real symmetric, bandwidth 2
__device__ __forceinline__ double Aval(int x, int y) {
    if (y < 0 || y >= DIM) return 0.0;
    int d = x - y;
    if (d < 0) d = -d;
    if (d > 2) return 0.0;
    if (d == 0) return g_aDiag[x];
    if (d == 1) return g_aOff1[x < y ? x : y];
    return THETA * THETA * 0.8187307530779818586699355086383; // theta^2*exp(-0.2)
}

// Band-only kernel over a pre-zeroed output. 16 thread-slots per row, 9 live
// (diagonals d = -4..+4; Re part of A*herm(H0)*A + algebra + reg).
// No transcendentals: everything table-fed. ~20 DFMAs per live thread.
__global__ void band_kernel(float* __restrict__ out) {
    int t = blockIdx.x * blockDim.x + threadIdx.x;   // exact DIM*16
    int i = t >> 4;
    int slot = t & 15;
    if (slot >= 9) return;
    int j = i + slot - 4;
    if (j < 0 || j >= DIM) return;

    double sre = 0.0;
    #pragma unroll
    for (int kk = -2; kk <= 2; kk++) {
        int k = i + kk;
        if (k < 0 || k >= DIM) continue;
        sre += Aval(i, k) * g_dDiag[k] * Aval(j, k);
    }
    int d = i - j;
    if (d == 0) {
        sre += REGEPS;
    } else if (d == 2 || d == -2) {
        sre += g_exp2[(i < j) ? i : j];
    }
    out[i * DIM + j] = (float)sre;
}

// Fallback for unexpected out_size (kept for safety; out_size==DIM*DIM confirmed)
__global__ void fill_generic_f32(float* __restrict__ out, int n) {
    int idx = blockIdx.x * blockDim.x + threadIdx.x;
    if (idx >= n) return;
    int m = idx & (DIM * DIM - 1);
    int i = m >> 11, j = m & (DIM - 1);
    double sre = 0.0;
    #pragma unroll
    for (int kk = -2; kk <= 2; kk++) {
        int k = i + kk;
        if (k < 0 || k >= DIM) continue;
        sre += Aval(i, k) * g_dDiag[k] * Aval(j, k);
    }
    int d = i - j;
    if (d == 0) sre += REGEPS;
    else if (d == 2 || d == -2) sre += g_exp2[(i < j) ? i : j];
    out[idx] = (float)sre;
}

extern "C" void kernel_launch(void* const* d_in, const int* in_sizes, int n_in,
                              void* d_out, int out_size) {
    const float* s_real = (const float*)d_in[0];
    const float* s_imag = (const float*)((n_in >= 2) ? d_in[1] : d_in[0]);

    const int NTOT = DIM * DIM;
    if (out_size == NTOT) {
        // 1) engine-backed zero of the whole 16 MB output (graph memset node)
        cudaMemsetAsync(d_out, 0, (size_t)NTOT * sizeof(float));
        // 2) fp64 transcendentals quarantined to 2048 threads
        precompute_kernel<<<(DIM + 255) / 256, 256>>>(s_real, s_imag);
        // 3) band elements only: 2048 rows x 9 diagonals
        band_kernel<<<(DIM * 16) / 256, 256>>>((float*)d_out);
    } else {
        precompute_kernel<<<(DIM + 255) / 256, 256>>>(s_real, s_imag);
        fill_generic_f32<<<(out_size + 255) / 256, 256>>>((float*)d_out, out_size);
    }
}

// round 9
// speedup vs baseline: 2.7649x; 2.1369x over previous
#include <cuda_runtime.h>

#define DIM 2048
#define THETA 1e-18
#define REGEPS 1e-15

// first 50 primes (max 229)
__constant__ int c_primes[50] = {
    2,3,5,7,11,13,17,19,23,29,31,37,41,43,47,53,59,61,67,71,
    73,79,83,89,97,101,103,107,109,113,127,131,137,139,149,151,157,163,167,173,
    179,181,191,193,197,199,211,223,227,229};

#define ROWS_PER_CTA 16
#define HALO 8
#define TBL 32   // ROWS_PER_CTA + 2*HALO

// Single fused kernel: per-CTA shared tables + slab zero-fill + band writes.
// CTA c owns rows [16c, 16c+16). All needed table indices lie in [16c-5, 16c+19],
// covered by the 32-entry halo window [16c-8, 16c+24).
__global__ void __launch_bounds__(256, 1)
fused_kernel(const float* __restrict__ s_real,
             const float* __restrict__ s_imag,
             float* __restrict__ out) {
    __shared__ double sA[TBL];   // Arnold diag
    __shared__ double sO[TBL];   // Arnold off-1 (at min index)
    __shared__ double sD[TBL];   // Re(n^{-s}) + prime diag corr
    __shared__ double sE[TBL];   // |s|*theta^2*exp(-0.01*m)

    const int base = blockIdx.x * ROWS_PER_CTA;
    const int t = threadIdx.x;
    const double PI = 3.141592653589793238462643383279502884;

    // ---- Phase A: tables (96 threads, ~2 transcendental chains each) ----
    if (t < 96) {
        int fam = t >> 5;
        int lm  = t & 31;
        int m   = base - HALO + lm;
        bool ok = (m >= 0 && m < DIM);
        if (fam == 0) {
            sA[lm] = ok ? 1.0 + THETA * cos(2.0 * PI * (double)m / (double)DIM) : 0.0;
            sO[lm] = (ok && m < DIM - 1)
                       ? THETA * sin(PI * (2.0 * (double)m + 1.0) / (double)DIM) : 0.0;
        } else if (fam == 1) {
            double dv = 0.0;
            if (ok) {
                int n = m + 1;
                double ln_n = log((double)n);
                bool isp = false;
                #pragma unroll
                for (int p = 0; p < 50; p++) isp |= (c_primes[p] == n);
                double sr = (double)s_real[0];
                double si = (double)s_imag[0];
                dv = exp(-sr * ln_n) * cos(si * ln_n);       // Re(n^{-s})
                if (isp) dv += THETA * ln_n * (PI * PI / 6.0);
            }
            sD[lm] = dv;
        } else {
            double ev = 0.0;
            if (ok) {
                double sr = (double)s_real[0];
                double si = (double)s_imag[0];
                ev = sqrt(sr * sr + si * si) * THETA * THETA * exp(-0.01 * (double)m);
            }
            sE[lm] = ev;
        }
    }

    // ---- Phase B: zero this CTA's 16-row slab (16*2048 floats = 8192 float4) ----
    {
        float4* o4 = (float4*)(out + (size_t)base * DIM);
        const float4 z = make_float4(0.f, 0.f, 0.f, 0.f);
        #pragma unroll
        for (int r = 0; r < 32; r++) o4[t + 256 * r] = z;
    }

    __syncthreads();   // tables visible; zero-stores ordered before band writes

    // ---- Phase C: band elements (9 diagonals per row) ----
    int r = t >> 4;             // 0..15 row within slab
    int slot = t & 15;
    if (slot < 9) {
        int i = base + r;
        int j = i + slot - 4;
        if (j >= 0 && j < DIM) {
            auto aval = [&](int x, int y) -> double {
                if (y < 0 || y >= DIM) return 0.0;
                int dd = x - y; dd = dd < 0 ? -dd : dd;
                if (dd > 2) return 0.0;
                if (dd == 0) return sA[x - base + HALO];
                if (dd == 1) return sO[(x < y ? x : y) - base + HALO];
                return THETA * THETA * 0.8187307530779818586699355086383;
            };
            double sre = 0.0;
            #pragma unroll
            for (int kk = -2; kk <= 2; kk++) {
                int k = i + kk;
                if (k < 0 || k >= DIM) continue;
                sre += aval(i, k) * sD[k - base + HALO] * aval(j, k);
            }
            int d = i - j;
            if (d == 0)                 sre += REGEPS;
            else if (d == 2 || d == -2) sre += sE[((i < j) ? i : j) - base + HALO];
            out[(size_t)i * DIM + j] = (float)sre;
        }
    }
}

// ---------------- fallback path (unexpected out_size) ----------------
__device__ double g_aDiag[DIM];
__device__ double g_aOff1[DIM];
__device__ double g_dDiag[DIM];
__device__ double g_exp2[DIM];

__global__ void precompute_kernel(const float* __restrict__ s_real,
                                  const float* __restrict__ s_imag) {
    int m = blockIdx.x * blockDim.x + threadIdx.x;
    if (m >= DIM) return;
    const double PI = 3.141592653589793238462643383279502884;
    double sr = (double)s_real[0], si = (double)s_imag[0];
    g_aDiag[m] = 1.0 + THETA * cos(2.0 * PI * (double)m / (double)DIM);
    g_aOff1[m] = (m < DIM - 1) ? THETA * sin(PI * (2.0 * (double)m + 1.0) / (double)DIM) : 0.0;
    int n = m + 1;
    double ln_n = log((double)n);
    bool isp = false;
    #pragma unroll
    for (int p = 0; p < 50; p++) isp |= (c_primes[p] == n);
    double dv = exp(-sr * ln_n) * cos(si * ln_n);
    if (isp) dv += THETA * ln_n * (PI * PI / 6.0);
    g_dDiag[m] = dv;
    g_exp2[m] = sqrt(sr * sr + si * si) * THETA * THETA * exp(-0.01 * (double)m);
}

__device__ __forceinline__ double AvalG(int x, int y) {
    if (y < 0 || y >= DIM) return 0.0;
    int d = x - y; d = d < 0 ? -d : d;
    if (d > 2) return 0.0;
    if (d == 0) return g_aDiag[x];
    if (d == 1) return g_aOff1[x < y ? x : y];
    return THETA * THETA * 0.8187307530779818586699355086383;
}

__global__ void fill_generic_f32(float* __restrict__ out, int n) {
    int idx = blockIdx.x * blockDim.x + threadIdx.x;
    if (idx >= n) return;
    int m = idx & (DIM * DIM - 1);
    int i = m >> 11, j = m & (DIM - 1);
    double sre = 0.0;
    #pragma unroll
    for (int kk = -2; kk <= 2; kk++) {
        int k = i + kk;
        if (k < 0 || k >= DIM) continue;
        sre += AvalG(i, k) * g_dDiag[k] * AvalG(j, k);
    }
    int d = i - j;
    if (d == 0) sre += REGEPS;
    else if (d == 2 || d == -2) sre += g_exp2[(i < j) ? i : j];
    out[idx] = (float)sre;
}

extern "C" void kernel_launch(void* const* d_in, const int* in_sizes, int n_in,
                              void* d_out, int out_size) {
    const float* s_real = (const float*)d_in[0];
    const float* s_imag = (const float*)((n_in >= 2) ? d_in[1] : d_in[0]);

    const int NTOT = DIM * DIM;
    if (out_size == NTOT) {
        fused_kernel<<<DIM / ROWS_PER_CTA, 256>>>(s_real, s_imag, (float*)d_out);
    } else {
        precompute_kernel<<<(DIM + 255) / 256, 256>>>(s_real, s_imag);
        fill_generic_f32<<<(out_size + 255) / 256, 256>>>((float*)d_out, out_size);
    }
}

// round 10
// speedup vs baseline: 3.3297x; 1.2043x over previous
#include <cuda_runtime.h>

#define DIM 2048
#define THETA 1e-18
#define REGEPS 1e-15

// first 50 primes (max 229)
__constant__ int c_primes[50] = {
    2,3,5,7,11,13,17,19,23,29,31,37,41,43,47,53,59,61,67,71,
    73,79,83,89,97,101,103,107,109,113,127,131,137,139,149,151,157,163,167,173,
    179,181,191,193,197,199,211,223,227,229};

#define ROWS_PER_CTA 16
#define HALO 8
#define TBL 32   // ROWS_PER_CTA + 2*HALO

// Single fused kernel: per-CTA shared tables (fp32 transcendentals, fp64 hold),
// slab zero-fill, band writes. CTA c owns rows [16c, 16c+16); table window
// [16c-8, 16c+24) covers all band needs [16c-5, 16c+19].
__global__ void __launch_bounds__(256, 1)
fused_kernel(const float* __restrict__ s_real,
             const float* __restrict__ s_imag,
             float* __restrict__ out) {
    __shared__ double sA[TBL];   // Arnold diag
    __shared__ double sO[TBL];   // Arnold off-1 (indexed by min index)
    __shared__ double sD[TBL];   // Re(n^{-s}) + prime diag corr
    __shared__ double sE[TBL];   // |s|*theta^2*exp(-0.01*m)

    const int base = blockIdx.x * ROWS_PER_CTA;
    const int t = threadIdx.x;
    const float PIf = 3.14159265358979323846f;

    // ---- Phase A: tables via fp32 MUFU transcendentals (96 threads) ----
    if (t < 96) {
        int fam = t >> 5;
        int lm  = t & 31;
        int m   = base - HALO + lm;
        bool ok = (m >= 0 && m < DIM);
        float srf = s_real[0];
        float sif = s_imag[0];
        if (fam == 0) {
            // 1 + theta*cos rounds to exactly 1.0 (theta << eps) — same as ref f64
            sA[lm] = 1.0;
            sO[lm] = (ok && m < DIM - 1)
                       ? (double)(THETA) * (double)sinf(PIf * (2.0f * (float)m + 1.0f) / (float)DIM)
                       : 0.0;
        } else if (fam == 1) {
            double dv = 0.0;
            if (ok) {
                int n = m + 1;
                float ln_n = logf((float)n);
                bool isp = false;
                #pragma unroll
                for (int p = 0; p < 50; p++) isp |= (c_primes[p] == n);
                // Re(n^{-s}) = exp(-sr*ln n) * cos(si*ln n)
                float mag = expf(-srf * ln_n);
                float ph  = cosf(sif * ln_n);
                dv = (double)mag * (double)ph;
                if (isp) dv += THETA * (double)ln_n * 1.6449340668482264; // zeta(2)
            }
            sD[lm] = dv;
        } else {
            double ev = 0.0;
            if (ok) {
                float abss = sqrtf(srf * srf + sif * sif);
                // keep the tiny-magnitude product in double (result ~1e-35..1e-44)
                ev = (double)abss * (THETA * THETA) * (double)expf(-0.01f * (float)m);
            }
            sE[lm] = ev;
        }
    }

    // ---- Phase B: zero this CTA's 16-row slab (8192 float4) ----
    {
        float4* o4 = (float4*)(out + (size_t)base * DIM);
        const float4 z = make_float4(0.f, 0.f, 0.f, 0.f);
        #pragma unroll
        for (int r = 0; r < 32; r++) o4[t + 256 * r] = z;
    }

    __syncthreads();   // tables visible; zeros ordered before band overwrites

    // ---- Phase C: band elements (9 diagonals per row), fp64 accumulation ----
    int r = t >> 4;
    int slot = t & 15;
    if (slot < 9) {
        int i = base + r;
        int j = i + slot - 4;
        if (j >= 0 && j < DIM) {
            auto aval = [&](int x, int y) -> double {
                if (y < 0 || y >= DIM) return 0.0;
                int dd = x - y; dd = dd < 0 ? -dd : dd;
                if (dd > 2) return 0.0;
                if (dd == 0) return sA[x - base + HALO];
                if (dd == 1) return sO[(x < y ? x : y) - base + HALO];
                return THETA * THETA * 0.8187307530779818586699355086383;
            };
            double sre = 0.0;
            #pragma unroll
            for (int kk = -2; kk <= 2; kk++) {
                int k = i + kk;
                if (k < 0 || k >= DIM) continue;
                sre += aval(i, k) * sD[k - base + HALO] * aval(j, k);
            }
            int d = i - j;
            if (d == 0)                 sre += REGEPS;
            else if (d == 2 || d == -2) sre += sE[((i < j) ? i : j) - base + HALO];
            out[(size_t)i * DIM + j] = (float)sre;
        }
    }
}

// ---------------- fallback path (unexpected out_size; fp64 reference math) ----
__device__ double g_aDiag[DIM];
__device__ double g_aOff1[DIM];
__device__ double g_dDiag[DIM];
__device__ double g_exp2[DIM];

__global__ void precompute_kernel(const float* __restrict__ s_real,
                                  const float* __restrict__ s_imag) {
    int m = blockIdx.x * blockDim.x + threadIdx.x;
    if (m >= DIM) return;
    const double PI = 3.141592653589793238462643383279502884;
    double sr = (double)s_real[0], si = (double)s_imag[0];
    g_aDiag[m] = 1.0 + THETA * cos(2.0 * PI * (double)m / (double)DIM);
    g_aOff1[m] = (m < DIM - 1) ? THETA * sin(PI * (2.0 * (double)m + 1.0) / (double)DIM) : 0.0;
    int n = m + 1;
    double ln_n = log((double)n);
    bool isp = false;
    #pragma unroll
    for (int p = 0; p < 50; p++) isp |= (c_primes[p] == n);
    double dv = exp(-sr * ln_n) * cos(si * ln_n);
    if (isp) dv += THETA * ln_n * (PI * PI / 6.0);
    g_dDiag[m] = dv;
    g_exp2[m] = sqrt(sr * sr + si * si) * THETA * THETA * exp(-0.01 * (double)m);
}

__device__ __forceinline__ double AvalG(int x, int y) {
    if (y < 0 || y >= DIM) return 0.0;
    int d = x - y; d = d < 0 ? -d : d;
    if (d > 2) return 0.0;
    if (d == 0) return g_aDiag[x];
    if (d == 1) return g_aOff1[x < y ? x : y];
    return THETA * THETA * 0.8187307530779818586699355086383;
}

__global__ void fill_generic_f32(float* __restrict__ out, int n) {
    int idx = blockIdx.x * blockDim.x + threadIdx.x;
    if (idx >= n) return;
    int m = idx & (DIM * DIM - 1);
    int i = m >> 11, j = m & (DIM - 1);
    double sre = 0.0;
    #pragma unroll
    for (int kk = -2; kk <= 2; kk++) {
        int k = i + kk;
        if (k < 0 || k >= DIM) continue;
        sre += AvalG(i, k) * g_dDiag[k] * AvalG(j, k);
    }
    int d = i - j;
    if (d == 0) sre += REGEPS;
    else if (d == 2 || d == -2) sre += g_exp2[(i < j) ? i : j];
    out[idx] = (float)sre;
}

extern "C" void kernel_launch(void* const* d_in, const int* in_sizes, int n_in,
                              void* d_out, int out_size) {
    const float* s_real = (const float*)d_in[0];
    const float* s_imag = (const float*)((n_in >= 2) ? d_in[1] : d_in[0]);

    const int NTOT = DIM * DIM;
    if (out_size == NTOT) {
        fused_kernel<<<DIM / ROWS_PER_CTA, 256>>>(s_real, s_imag, (float*)d_out);
    } else {
        precompute_kernel<<<(DIM + 255) / 256, 256>>>(s_real, s_imag);
        fill_generic_f32<<<(out_size + 255) / 256, 256>>>((float*)d_out, out_size);
    }
}

// round 11
// speedup vs baseline: 3.4280x; 1.0295x over previous
#include <cuda_runtime.h>

#define DIM 2048
#define THETA 1e-18
#define REGEPS 1e-15

// first 50 primes (max 229)
__constant__ int c_primes[50] = {
    2,3,5,7,11,13,17,19,23,29,31,37,41,43,47,53,59,61,67,71,
    73,79,83,89,97,101,103,107,109,113,127,131,137,139,149,151,157,163,167,173,
    179,181,191,193,197,199,211,223,227,229};

#define ROWS_PER_CTA 8
#define HALO 8
#define TBL 24   // ROWS_PER_CTA + 2*HALO; band needs [base-6, base+11] ⊂ [base-8, base+16)

// Single fused kernel. CTA c owns rows [8c, 8c+8). 256 CTAs → every SM busy,
// ~2 CTAs/SM resident pushing STG.128 in parallel (goal: saturate LTS write path).
__global__ void __launch_bounds__(256, 2)
fused_kernel(const float* __restrict__ s_real,
             const float* __restrict__ s_imag,
             float* __restrict__ out) {
    __shared__ double sA[TBL];   // Arnold diag (== 1.0 exactly; theta << eps64)
    __shared__ double sO[TBL];   // Arnold off-1 (indexed by min index)
    __shared__ double sD[TBL];   // Re(n^{-s}) + prime diag corr
    __shared__ double sE[TBL];   // |s|*theta^2*exp(-0.01*m)

    const int base = blockIdx.x * ROWS_PER_CTA;
    const int t = threadIdx.x;
    const float PIf = 3.14159265358979323846f;

    // ---- Phase A: tables via fp32 MUFU transcendentals (3 warps, 24 lanes each) ----
    if (t < 96) {
        int fam = t >> 5;
        int lm  = t & 31;
        if (lm < TBL) {
            int m  = base - HALO + lm;
            bool ok = (m >= 0 && m < DIM);
            float srf = s_real[0];
            float sif = s_imag[0];
            if (fam == 0) {
                sA[lm] = 1.0;  // 1 + theta*cos rounds to exactly 1.0 in f64 too
                sO[lm] = (ok && m < DIM - 1)
                           ? (double)(THETA) * (double)sinf(PIf * (2.0f * (float)m + 1.0f) / (float)DIM)
                           : 0.0;
            } else if (fam == 1) {
                double dv = 0.0;
                if (ok) {
                    int n = m + 1;
                    float ln_n = logf((float)n);
                    bool isp = false;
                    #pragma unroll
                    for (int p = 0; p < 50; p++) isp |= (c_primes[p] == n);
                    float mag = expf(-srf * ln_n);     // Re(n^{-s}) = e^{-sr ln n} cos(si ln n)
                    float ph  = cosf(sif * ln_n);
                    dv = (double)mag * (double)ph;
                    if (isp) dv += THETA * (double)ln_n * 1.6449340668482264; // zeta(2)
                }
                sD[lm] = dv;
            } else {
                double ev = 0.0;
                if (ok) {
                    float abss = sqrtf(srf * srf + sif * sif);
                    ev = (double)abss * (THETA * THETA) * (double)expf(-0.01f * (float)m);
                }
                sE[lm] = ev;
            }
        }
    }

    // ---- Phase B: zero this CTA's 8-row slab (8*2048 floats = 4096 float4) ----
    {
        float4* o4 = (float4*)(out + (size_t)base * DIM);
        const float4 z = make_float4(0.f, 0.f, 0.f, 0.f);
        #pragma unroll
        for (int r = 0; r < 16; r++) o4[t + 256 * r] = z;
    }

    __syncthreads();   // tables visible; zeros ordered before band overwrites

    // ---- Phase C: band elements (9 diagonals per row), fp64 accumulation ----
    int r = t >> 4;              // 0..15, but only r<8 rows live
    int slot = t & 15;
    if (r < ROWS_PER_CTA && slot < 9) {
        int i = base + r;
        int j = i + slot - 4;
        if (j >= 0 && j < DIM) {
            auto aval = [&](int x, int y) -> double {
                if (y < 0 || y >= DIM) return 0.0;
                int dd = x - y; dd = dd < 0 ? -dd : dd;
                if (dd > 2) return 0.0;
                if (dd == 0) return sA[x - base + HALO];
                if (dd == 1) return sO[(x < y ? x : y) - base + HALO];
                return THETA * THETA * 0.8187307530779818586699355086383;
            };
            double sre = 0.0;
            #pragma unroll
            for (int kk = -2; kk <= 2; kk++) {
                int k = i + kk;
                if (k < 0 || k >= DIM) continue;
                sre += aval(i, k) * sD[k - base + HALO] * aval(j, k);
            }
            int d = i - j;
            if (d == 0)                 sre += REGEPS;
            else if (d == 2 || d == -2) sre += sE[((i < j) ? i : j) - base + HALO];
            out[(size_t)i * DIM + j] = (float)sre;
        }
    }
}

// ---------------- fallback path (unexpected out_size; fp64 reference math) ----
__device__ double g_aDiag[DIM];
__device__ double g_aOff1[DIM];
__device__ double g_dDiag[DIM];
__device__ double g_exp2[DIM];

__global__ void precompute_kernel(const float* __restrict__ s_real,
                                  const float* __restrict__ s_imag) {
    int m = blockIdx.x * blockDim.x + threadIdx.x;
    if (m >= DIM) return;
    const double PI = 3.141592653589793238462643383279502884;
    double sr = (double)s_real[0], si = (double)s_imag[0];
    g_aDiag[m] = 1.0 + THETA * cos(2.0 * PI * (double)m / (double)DIM);
    g_aOff1[m] = (m < DIM - 1) ? THETA * sin(PI * (2.0 * (double)m + 1.0) / (double)DIM) : 0.0;
    int n = m + 1;
    double ln_n = log((double)n);
    bool isp = false;
    #pragma unroll
    for (int p = 0; p < 50; p++) isp |= (c_primes[p] == n);
    double dv = exp(-sr * ln_n) * cos(si * ln_n);
    if (isp) dv += THETA * ln_n * (PI * PI / 6.0);
    g_dDiag[m] = dv;
    g_exp2[m] = sqrt(sr * sr + si * si) * THETA * THETA * exp(-0.01 * (double)m);
}

__device__ __forceinline__ double AvalG(int x, int y) {
    if (y < 0 || y >= DIM) return 0.0;
    int d = x - y; d = d < 0 ? -d : d;
    if (d > 2) return 0.0;
    if (d == 0) return g_aDiag[x];
    if (d == 1) return g_aOff1[x < y ? x : y];
    return THETA * THETA * 0.8187307530779818586699355086383;
}

__global__ void fill_generic_f32(float* __restrict__ out, int n) {
    int idx = blockIdx.x * blockDim.x + threadIdx.x;
    if (idx >= n) return;
    int m = idx & (DIM * DIM - 1);
    int i = m >> 11, j = m & (DIM - 1);
    double sre = 0.0;
    #pragma unroll
    for (int kk = -2; kk <= 2; kk++) {
        int k = i + kk;
        if (k < 0 || k >= DIM) continue;
        sre += AvalG(i, k) * g_dDiag[k] * AvalG(j, k);
    }
    int d = i - j;
    if (d == 0) sre += REGEPS;
    else if (d == 2 || d == -2) sre += g_exp2[(i < j) ? i : j];
    out[idx] = (float)sre;
}

extern "C" void kernel_launch(void* const* d_in, const int* in_sizes, int n_in,
                              void* d_out, int out_size) {
    const float* s_real = (const float*)d_in[0];
    const float* s_imag = (const float*)((n_in >= 2) ? d_in[1] : d_in[0]);

    const int NTOT = DIM * DIM;
    if (out_size == NTOT) {
        fused_kernel<<<DIM / ROWS_PER_CTA, 256>>>(s_real, s_imag, (float*)d_out);
    } else {
        precompute_kernel<<<(DIM + 255) / 256, 256>>>(s_real, s_imag);
        fill_generic_f32<<<(out_size + 255) / 256, 256>>>((float*)d_out, out_size);
    }
}